// round 4
// baseline (speedup 1.0000x reference)
#include <cuda_runtime.h>

// Fixed shapes
#define HH 256
#define WW 512
#define HW (HH * WW)                 // 131072 floats/plane
#define HW4 (HW / 4)                 // 32768 float4/plane
#define W4 (WW / 4)                  // 128 float4/row
#define NSTUFF 11
#define STUFF4 (NSTUFF * HW4)
#define TPB 256
#define ITERS (HW4 / TPB)            // 128 float4 per thread (whole plane per block)
#define NBOX 128

__global__ __launch_bounds__(TPB) void seg_term_kernel(
    const int*    __restrict__ cls,     // [128]
    const float*  __restrict__ seg,     // [19*HW]
    const float*  __restrict__ boxes,   // [128*5]
    float*        __restrict__ out)
{
    const int b   = blockIdx.x;
    const int tid = threadIdx.x;
    const float4 z = make_float4(0.f, 0.f, 0.f, 0.f);

    if (b < NSTUFF) {
        // ---- stuff plane copy: one plane per block, MLP-4 load/store groups ----
        const float4* s4 = reinterpret_cast<const float4*>(seg) + b * HW4;
        float4*       o4 = reinterpret_cast<float4*>(out)       + b * HW4;
        #pragma unroll 4
        for (int i = 0; i < ITERS; i += 4) {
            float4 v0 = s4[tid + (i + 0) * TPB];
            float4 v1 = s4[tid + (i + 1) * TPB];
            float4 v2 = s4[tid + (i + 2) * TPB];
            float4 v3 = s4[tid + (i + 3) * TPB];
            o4[tid + (i + 0) * TPB] = v0;
            o4[tid + (i + 1) * TPB] = v1;
            o4[tid + (i + 2) * TPB] = v2;
            o4[tid + (i + 3) * TPB] = v3;
        }
        return;
    }

    // ---- instance plane: one plane per block, params loaded ONCE ----
    const int n = b - NSTUFF;
    float4* o4 = reinterpret_cast<float4*>(out) + STUFF4 + n * HW4;

    const int c = __ldg(cls + n);

    int x0 = 0, y0 = 0, x1 = 0, y1 = 0, m = 0;
    bool any = false;
    if (c != 0) {
        const float* bb = boxes + n * 5;
        x0 = (int)floorf(__ldg(bb + 1) * 0.25f);
        y0 = (int)floorf(__ldg(bb + 2) * 0.25f);
        x1 = (int)(rintf(__ldg(bb + 3) * 0.25f) + 1.0f);  // half-even, matches jnp.round
        y1 = (int)(rintf(__ldg(bb + 4) * 0.25f) + 1.0f);
        m  = (c + 10 > 18) ? 18 : c + 10;
        any = (x1 > x0) && (y1 > y0) && (y1 > 0) && (y0 < HH) && (x1 > 0) && (x0 < WW);
    }

    if (!any) {
        // pure zero-fill: 128 STG.128 per thread, same source quad (minimal regs)
        #pragma unroll 8
        for (int i = 0; i < ITERS; i++)
            o4[tid + i * TPB] = z;
        return;
    }

    const float4* s4 = reinterpret_cast<const float4*>(seg) + m * HW4;

    // Each iteration covers 2 full rows (256 float4 = 2 rows of 128).
    // Row/col for this thread are loop-invariant apart from +2 on y.
    const int xf4 = tid & (W4 - 1);          // float4 column (0..127)
    const int x   = xf4 << 2;                // first scalar col of this float4
    int y = tid >> 7;                        // starting row (0 or 1)

    // Column classification is loop-invariant:
    const bool col_full = (x >= x0) && ((x + 3) < x1);
    const bool col_edge = !col_full && ((x + 3) >= x0) && (x < x1);

    #pragma unroll 4
    for (int i = 0; i < ITERS; i++, y += 2) {
        const int idx = tid + i * TPB;
        float4 v = z;
        if (y >= y0 && y < y1) {
            if (col_full) {
                v = s4[idx];
            } else if (col_edge) {
                const float* sr = reinterpret_cast<const float*>(s4 + idx);
                float vv[4];
                #pragma unroll
                for (int j = 0; j < 4; j++) {
                    const int xx = x + j;
                    vv[j] = (xx >= x0 && xx < x1) ? sr[j] : 0.f;
                }
                v = make_float4(vv[0], vv[1], vv[2], vv[3]);
            }
        }
        o4[idx] = v;
    }
}

extern "C" void kernel_launch(void* const* d_in, const int* in_sizes, int n_in,
                              void* d_out, int out_size)
{
    const int*   cls   = (const int*)d_in[0];
    const float* seg   = (const float*)d_in[1];
    const float* boxes = (const float*)d_in[2];
    float* out = (float*)d_out;

    seg_term_kernel<<<NSTUFF + NBOX, TPB>>>(cls, seg, boxes, out);  // 139 blocks, 1 wave
}

// round 5
// speedup vs baseline: 1.4785x; 1.4785x over previous
#include <cuda_runtime.h>

// Fixed shapes
#define HH 256
#define WW 512
#define HW (HH * WW)                 // floats per plane
#define HW4 (HW / 4)                 // 32768 float4/plane
#define W4 (WW / 4)                  // 128 float4/row
#define NSTUFF 11
#define STUFF4 (NSTUFF * HW4)
#define TPB 256
#define ITEMS 8                      // float4 per thread per chunk
#define F4_PER_CHUNK (TPB * ITEMS)   // 2048 float4 (16 rows)
#define ROWS_PER_CHUNK 16
#define STUFF_CHUNKS (STUFF4 / F4_PER_CHUNK)     // 176
#define CHUNKS_PER_PLANE (HW4 / F4_PER_CHUNK)    // 16
#define NBOX 128
#define TOTAL_CHUNKS (STUFF_CHUNKS + NBOX * CHUNKS_PER_PLANE)  // 2224
#define GRID 556                     // 2224 / 556 = 4 chunks per CTA, single wave

__global__ __launch_bounds__(TPB) void seg_term_kernel(
    const int*    __restrict__ cls,     // [128]
    const float*  __restrict__ seg,     // [19*HW]
    const float*  __restrict__ boxes,   // [128*5]
    float*        __restrict__ out)
{
    __shared__ int sx0[NBOX], sx1[NBOX], sy0[NBOX], sy1[NBOX], sm_[NBOX]; // sm_<0 => inactive

    const int tid = threadIdx.x;
    const float4 z = make_float4(0.f, 0.f, 0.f, 0.f);

    // ---- one-time prologue: resolve every box's params into SMEM ----
    if (tid < NBOX) {
        const int c = __ldg(cls + tid);
        int x0 = 0, y0 = 0, x1 = 0, y1 = 0, m = -1;
        if (c != 0) {
            const float* bb = boxes + tid * 5;
            x0 = (int)floorf(__ldg(bb + 1) * 0.25f);
            y0 = (int)floorf(__ldg(bb + 2) * 0.25f);
            x1 = (int)(rintf(__ldg(bb + 3) * 0.25f) + 1.0f);  // half-even = jnp.round
            y1 = (int)(rintf(__ldg(bb + 4) * 0.25f) + 1.0f);
            if (x1 > x0 && y1 > y0 && x1 > 0 && x0 < WW && y1 > 0 && y0 < HH)
                m = (c + 10 > 18) ? 18 : c + 10;
        }
        sx0[tid] = x0; sy0[tid] = y0; sx1[tid] = x1; sy1[tid] = y1; sm_[tid] = m;
    }
    __syncthreads();

    // ---- persistent chunk loop: 4 chunks per CTA, single wave ----
    for (int ch = blockIdx.x; ch < TOTAL_CHUNKS; ch += GRID) {

        if (ch < STUFF_CHUNKS) {
            // stuff copy chunk: 8 batched loads then 8 stores
            const float4* s4 = reinterpret_cast<const float4*>(seg) + ch * F4_PER_CHUNK;
            float4*       o4 = reinterpret_cast<float4*>(out)       + ch * F4_PER_CHUNK;
            float4 v[ITEMS];
            #pragma unroll
            for (int k = 0; k < ITEMS; k++) v[k] = s4[tid + k * TPB];
            #pragma unroll
            for (int k = 0; k < ITEMS; k++) o4[tid + k * TPB] = v[k];
            continue;
        }

        const int ic  = ch - STUFF_CHUNKS;
        const int n   = ic >> 4;                     // plane index
        const int blk = ic & (CHUNKS_PER_PLANE - 1);
        const int r0  = blk * ROWS_PER_CHUNK;

        float4* o4 = reinterpret_cast<float4*>(out) + STUFF4 + n * HW4 + blk * F4_PER_CHUNK;

        const int m = sm_[n];
        const int y0 = sy0[n], y1 = sy1[n];

        if (m < 0 || y1 <= r0 || y0 >= r0 + ROWS_PER_CHUNK) {
            // zero burst
            #pragma unroll
            for (int k = 0; k < ITEMS; k++) o4[tid + k * TPB] = z;
            continue;
        }

        const int x0 = sx0[n], x1 = sx1[n];
        const float4* s4 = reinterpret_cast<const float4*>(seg) + m * HW4 + blk * F4_PER_CHUNK;

        const int x = (tid & (W4 - 1)) << 2;         // first scalar col of this float4
        const bool col_full = (x >= x0) && ((x + 3) < x1);
        const bool col_edge = !col_full && ((x + 3) >= x0) && (x < x1);

        float4 v[ITEMS];
        #pragma unroll
        for (int k = 0; k < ITEMS; k++) {
            const int idx = tid + k * TPB;
            const int y   = r0 + (idx >> 7);
            v[k] = z;
            if (y >= y0 && y < y1) {
                if (col_full) {
                    v[k] = s4[idx];
                } else if (col_edge) {
                    const float* sr = reinterpret_cast<const float*>(s4 + idx);
                    float vv[4];
                    #pragma unroll
                    for (int j = 0; j < 4; j++) {
                        const int xx = x + j;
                        vv[j] = (xx >= x0 && xx < x1) ? sr[j] : 0.f;
                    }
                    v[k] = make_float4(vv[0], vv[1], vv[2], vv[3]);
                }
            }
        }
        #pragma unroll
        for (int k = 0; k < ITEMS; k++) o4[tid + k * TPB] = v[k];
    }
}

extern "C" void kernel_launch(void* const* d_in, const int* in_sizes, int n_in,
                              void* d_out, int out_size)
{
    const int*   cls   = (const int*)d_in[0];
    const float* seg   = (const float*)d_in[1];
    const float* boxes = (const float*)d_in[2];
    float* out = (float*)d_out;

    seg_term_kernel<<<GRID, TPB>>>(cls, seg, boxes, out);
}